// round 7
// baseline (speedup 1.0000x reference)
#include <cuda_runtime.h>
#include <math.h>

#define DH 1024
#define DM 1024
#define BATCH 128
static constexpr float QK_SCALE = 0.03125f; // 1/sqrt(1024)

// -------- scratch (no allocations allowed) --------
__device__ float g_q[BATCH * DH];
__device__ float g_k[BATCH * DH];
__device__ float g_v[BATCH * DH];
__device__ float g_o[BATCH * DH];
__device__ float g_hh[BATCH * DH];
__device__ float g_part[4][BATCH * DM];   // split-K partials for out_proj
__device__ float g_ip[BATCH];
__device__ float g_fp[BATCH];
__device__ float g_den[BATCH];

__device__ __forceinline__ float warp_sum(float v) {
    #pragma unroll
    for (int s = 16; s; s >>= 1) v += __shfl_xor_sync(0xffffffffu, v, s);
    return v;
}

// ============================================================
// Projections q/k/v/sigmoid(o)  (one batch-half per launch)
// BM=64, BN=32, BK=16, 128 threads, 4x4 thread tile.
// grid = (32 n-tiles, 1, 4 matrices). Double-buffered smem.
// ============================================================
#define SMS 68  // smem row stride in floats

__global__ void __launch_bounds__(128)
proj_kernel(const float* __restrict__ x,
            const float* __restrict__ Wq, const float* __restrict__ Wk,
            const float* __restrict__ Wv, const float* __restrict__ Wo,
            const float* __restrict__ Wob, int b0)
{
    __shared__ float Xs[2][16][SMS];      // 64 m-rows
    __shared__ float Ws[2][16][36];       // 32 n-rows

    const int z = blockIdx.z;
    const float* __restrict__ W = (z == 0) ? Wq : (z == 1) ? Wk : (z == 2) ? Wv : Wo;
    float* __restrict__ Y = (z == 0) ? g_q : (z == 1) ? g_k : (z == 2) ? g_v : g_o;

    const int m0 = b0;
    const int n0 = blockIdx.x * 32;
    const int tid = threadIdx.x;
    const int tx = tid & 7;               // n frag
    const int ty = tid >> 3;              // m frag

    const int xr = tid >> 1;              // 0..63
    const int xc = tid & 1;               // 0..1
    const int wr = tid >> 2;              // 0..31
    const int wc = tid & 3;               // 0..3

    const float* __restrict__ xg = x + (size_t)(m0 + xr) * DM + xc * 8;
    const float* __restrict__ wg = W + (size_t)(n0 + wr) * DM + wc * 4;

    float4 xv0 = *(const float4*)xg;
    float4 xv1 = *(const float4*)(xg + 4);
    float4 wv  = *(const float4*)wg;

    float acc[4][4] = {};
    int buf = 0;

    #pragma unroll 1
    for (int kt = 0; kt < 64; kt++) {
        {
            const int cb = xc * 8;
            Xs[buf][cb + 0][xr] = xv0.x; Xs[buf][cb + 1][xr] = xv0.y;
            Xs[buf][cb + 2][xr] = xv0.z; Xs[buf][cb + 3][xr] = xv0.w;
            Xs[buf][cb + 4][xr] = xv1.x; Xs[buf][cb + 5][xr] = xv1.y;
            Xs[buf][cb + 6][xr] = xv1.z; Xs[buf][cb + 7][xr] = xv1.w;
            Ws[buf][wc * 4 + 0][wr] = wv.x; Ws[buf][wc * 4 + 1][wr] = wv.y;
            Ws[buf][wc * 4 + 2][wr] = wv.z; Ws[buf][wc * 4 + 3][wr] = wv.w;
        }
        __syncthreads();
        if (kt + 1 < 64) {
            xv0 = *(const float4*)(xg + (kt + 1) * 16);
            xv1 = *(const float4*)(xg + (kt + 1) * 16 + 4);
            wv  = *(const float4*)(wg + (kt + 1) * 16);
        }
        #pragma unroll
        for (int k = 0; k < 16; k++) {
            const float4 a = *(const float4*)&Xs[buf][k][ty * 4];
            const float4 w = *(const float4*)&Ws[buf][k][tx * 4];
            acc[0][0] = fmaf(a.x, w.x, acc[0][0]); acc[0][1] = fmaf(a.x, w.y, acc[0][1]);
            acc[0][2] = fmaf(a.x, w.z, acc[0][2]); acc[0][3] = fmaf(a.x, w.w, acc[0][3]);
            acc[1][0] = fmaf(a.y, w.x, acc[1][0]); acc[1][1] = fmaf(a.y, w.y, acc[1][1]);
            acc[1][2] = fmaf(a.y, w.z, acc[1][2]); acc[1][3] = fmaf(a.y, w.w, acc[1][3]);
            acc[2][0] = fmaf(a.z, w.x, acc[2][0]); acc[2][1] = fmaf(a.z, w.y, acc[2][1]);
            acc[2][2] = fmaf(a.z, w.z, acc[2][2]); acc[2][3] = fmaf(a.z, w.w, acc[2][3]);
            acc[3][0] = fmaf(a.w, w.x, acc[3][0]); acc[3][1] = fmaf(a.w, w.y, acc[3][1]);
            acc[3][2] = fmaf(a.w, w.z, acc[3][2]); acc[3][3] = fmaf(a.w, w.w, acc[3][3]);
        }
        __syncthreads();
        buf ^= 1;
    }

    #pragma unroll
    for (int i = 0; i < 4; i++) {
        const int m = m0 + ty * 4 + i;
        const int nb = n0 + tx * 4;
        float4 y;
        if (z == 3) {
            y.x = 1.f / (1.f + expf(-(acc[i][0] + Wob[nb + 0])));
            y.y = 1.f / (1.f + expf(-(acc[i][1] + Wob[nb + 1])));
            y.z = 1.f / (1.f + expf(-(acc[i][2] + Wob[nb + 2])));
            y.w = 1.f / (1.f + expf(-(acc[i][3] + Wob[nb + 3])));
        } else if (z == 2) {
            y.x = acc[i][0]; y.y = acc[i][1]; y.z = acc[i][2]; y.w = acc[i][3];
        } else {
            y.x = acc[i][0] * QK_SCALE; y.y = acc[i][1] * QK_SCALE;
            y.z = acc[i][2] * QK_SCALE; y.w = acc[i][3] * QK_SCALE;
        }
        *(float4*)&Y[(size_t)m * DH + nb] = y;
    }
}

// ============================================================
// Merged gating + n_t + denom (one block per batch, half grid)
// ============================================================
__global__ void __launch_bounds__(256)
gate_ndenom_kernel(const float* __restrict__ x,
                   const float* __restrict__ wi, const float* __restrict__ wib,
                   const float* __restrict__ wf, const float* __restrict__ wfb,
                   const float* __restrict__ mprev,
                   const float* __restrict__ nprev,
                   float* __restrict__ out_m, float* __restrict__ out_n, int b0)
{
    const int b = b0 + blockIdx.x;
    const int t = threadIdx.x;

    const float4 xv = ((const float4*)(x + (size_t)b * DM))[t];
    const float4 iv = ((const float4*)wi)[t];
    const float4 fv = ((const float4*)wf)[t];
    float si = xv.x * iv.x + xv.y * iv.y + xv.z * iv.z + xv.w * iv.w;
    float sf = xv.x * fv.x + xv.y * fv.y + xv.z * fv.z + xv.w * fv.w;

    __shared__ float sbi[8], sbf[8], sgate[2];
    si = warp_sum(si); sf = warp_sum(sf);
    if ((t & 31) == 0) { sbi[t >> 5] = si; sbf[t >> 5] = sf; }
    __syncthreads();
    if (t == 0) {
        float zi = 0.f, zf = 0.f;
        #pragma unroll
        for (int w = 0; w < 8; w++) { zi += sbi[w]; zf += sbf[w]; }
        zi += *wib; zf += *wfb;
        const float mp = mprev[b];
        const float mt = fmaxf(zf + mp, zi);
        const float ip = expf(zi - mt);
        const float fp = expf(zf + mp - mt);
        out_m[b] = mt;
        g_ip[b] = ip; g_fp[b] = fp;
        sgate[0] = ip; sgate[1] = fp;
    }
    __syncthreads();

    const float ip = sgate[0];
    const float f  = sgate[1];
    const float4 np = ((const float4*)(nprev + (size_t)b * DH))[t];
    const float4 kv = ((const float4*)(g_k   + (size_t)b * DH))[t];
    const float4 qv = ((const float4*)(g_q   + (size_t)b * DH))[t];
    float4 n;
    n.x = f * np.x + ip * kv.x;
    n.y = f * np.y + ip * kv.y;
    n.z = f * np.z + ip * kv.z;
    n.w = f * np.w + ip * kv.w;
    ((float4*)(out_n + (size_t)b * DH))[t] = n;

    float s = n.x * qv.x + n.y * qv.y + n.z * qv.z + n.w * qv.w;
    s = warp_sum(s);
    if ((t & 31) == 0) sbi[t >> 5] = s;
    __syncthreads();
    if (t == 0) {
        float tot = 0.f;
        #pragma unroll
        for (int w = 0; w < 8; w++) tot += sbi[w];
        g_den[b] = fmaxf(fabsf(tot), 1.f);
    }
}

// ============================================================
// Fused C update + Cq matvec + h_head  (HBM-bound, batch-half)
// grid (64 row-chunks, 64 batches), 512 threads = 16 warps.
// ============================================================
__global__ void __launch_bounds__(512)
c_update_kernel(const float* __restrict__ Cprev, float* __restrict__ Cout, int b0)
{
    const int b = b0 + blockIdx.y;
    __shared__ float4 ks4[256];
    __shared__ float4 qs4[256];
    if (threadIdx.x < 256) {
        const int t = threadIdx.x;
        ks4[t] = ((const float4*)(g_k + (size_t)b * DH))[t];
        qs4[t] = ((const float4*)(g_q + (size_t)b * DH))[t];
    }
    __syncthreads();

    const int warp = threadIdx.x >> 5;
    const int lane = threadIdx.x & 31;
    const int i = blockIdx.x * 16 + warp;

    const float f  = g_fp[b];
    const float iv = g_ip[b] * g_v[(size_t)b * DH + i];

    const float4* __restrict__ cp = (const float4*)(Cprev + ((size_t)b * DH + i) * DH);
    float4* __restrict__ co = (float4*)(Cout + ((size_t)b * DH + i) * DH);

    float4 c[8];
    #pragma unroll
    for (int u = 0; u < 8; u++) c[u] = __ldcs(&cp[u * 32 + lane]);

    float acc = 0.f;
    #pragma unroll
    for (int u = 0; u < 8; u++) {
        const int j4 = u * 32 + lane;
        const float4 k4 = ks4[j4];
        const float4 q4 = qs4[j4];
        float4 o;
        o.x = fmaf(f, c[u].x, iv * k4.x);
        o.y = fmaf(f, c[u].y, iv * k4.y);
        o.z = fmaf(f, c[u].z, iv * k4.z);
        o.w = fmaf(f, c[u].w, iv * k4.w);
        acc = fmaf(o.x, q4.x, acc);
        acc = fmaf(o.y, q4.y, acc);
        acc = fmaf(o.z, q4.z, acc);
        acc = fmaf(o.w, q4.w, acc);
        __stcs(&co[j4], o);
    }
    acc = warp_sum(acc);
    if (lane == 0)
        g_hh[(size_t)b * DH + i] = g_o[(size_t)b * DH + i] * acc / g_den[b];
}

// ============================================================
// out_proj split-K (batch-half): grid (32 n, 1, 4 ksplit), 128 thr
// ============================================================
__global__ void __launch_bounds__(128)
outproj_kernel(const float* __restrict__ P, int b0)
{
    __shared__ float Xs[2][16][SMS];
    __shared__ float Ws[2][16][36];

    const int z  = blockIdx.z;
    const int m0 = b0;
    const int n0 = blockIdx.x * 32;
    const int tid = threadIdx.x;
    const int tx = tid & 7;
    const int ty = tid >> 3;

    const int xr = tid >> 1, xc = tid & 1;
    const int wr = tid >> 2, wc = tid & 3;
    const int kbeg = z * 256;

    const float* __restrict__ xg = g_hh + (size_t)(m0 + xr) * DH + kbeg + xc * 8;
    const float* __restrict__ wg = P    + (size_t)(n0 + wr) * DH + kbeg + wc * 4;

    float4 xv0 = *(const float4*)xg;
    float4 xv1 = *(const float4*)(xg + 4);
    float4 wv  = *(const float4*)wg;

    float acc[4][4] = {};
    int buf = 0;

    #pragma unroll 1
    for (int kt = 0; kt < 16; kt++) {
        {
            const int cb = xc * 8;
            Xs[buf][cb + 0][xr] = xv0.x; Xs[buf][cb + 1][xr] = xv0.y;
            Xs[buf][cb + 2][xr] = xv0.z; Xs[buf][cb + 3][xr] = xv0.w;
            Xs[buf][cb + 4][xr] = xv1.x; Xs[buf][cb + 5][xr] = xv1.y;
            Xs[buf][cb + 6][xr] = xv1.z; Xs[buf][cb + 7][xr] = xv1.w;
            Ws[buf][wc * 4 + 0][wr] = wv.x; Ws[buf][wc * 4 + 1][wr] = wv.y;
            Ws[buf][wc * 4 + 2][wr] = wv.z; Ws[buf][wc * 4 + 3][wr] = wv.w;
        }
        __syncthreads();
        if (kt + 1 < 16) {
            xv0 = *(const float4*)(xg + (kt + 1) * 16);
            xv1 = *(const float4*)(xg + (kt + 1) * 16 + 4);
            wv  = *(const float4*)(wg + (kt + 1) * 16);
        }
        #pragma unroll
        for (int k = 0; k < 16; k++) {
            const float4 a = *(const float4*)&Xs[buf][k][ty * 4];
            const float4 w = *(const float4*)&Ws[buf][k][tx * 4];
            acc[0][0] = fmaf(a.x, w.x, acc[0][0]); acc[0][1] = fmaf(a.x, w.y, acc[0][1]);
            acc[0][2] = fmaf(a.x, w.z, acc[0][2]); acc[0][3] = fmaf(a.x, w.w, acc[0][3]);
            acc[1][0] = fmaf(a.y, w.x, acc[1][0]); acc[1][1] = fmaf(a.y, w.y, acc[1][1]);
            acc[1][2] = fmaf(a.y, w.z, acc[1][2]); acc[1][3] = fmaf(a.y, w.w, acc[1][3]);
            acc[2][0] = fmaf(a.z, w.x, acc[2][0]); acc[2][1] = fmaf(a.z, w.y, acc[2][1]);
            acc[2][2] = fmaf(a.z, w.z, acc[2][2]); acc[2][3] = fmaf(a.z, w.w, acc[2][3]);
            acc[3][0] = fmaf(a.w, w.x, acc[3][0]); acc[3][1] = fmaf(a.w, w.y, acc[3][1]);
            acc[3][2] = fmaf(a.w, w.z, acc[3][2]); acc[3][3] = fmaf(a.w, w.w, acc[3][3]);
        }
        __syncthreads();
        buf ^= 1;
    }

    float* __restrict__ Yp = g_part[z];
    #pragma unroll
    for (int i = 0; i < 4; i++) {
        const int m = m0 + ty * 4 + i;
        const int nb = n0 + tx * 4;
        float4 y;
        y.x = acc[i][0]; y.y = acc[i][1]; y.z = acc[i][2]; y.w = acc[i][3];
        *(float4*)&Yp[(size_t)m * DM + nb] = y;
    }
}

__global__ void __launch_bounds__(256)
outproj_reduce_kernel(float* __restrict__ out_h, int b0)
{
    const int idx = b0 * (DM / 4) + blockIdx.x * 256 + threadIdx.x; // float4 idx
    const float4 a = ((const float4*)g_part[0])[idx];
    const float4 b = ((const float4*)g_part[1])[idx];
    const float4 c = ((const float4*)g_part[2])[idx];
    const float4 d = ((const float4*)g_part[3])[idx];
    float4 r;
    r.x = (a.x + b.x) + (c.x + d.x);
    r.y = (a.y + b.y) + (c.y + d.y);
    r.z = (a.z + b.z) + (c.z + d.z);
    r.w = (a.w + b.w) + (c.w + d.w);
    ((float4*)out_h)[idx] = r;
}

// ============================================================
// stream/event setup (global ctor: before any harness checkpoint;
// no device-memory allocation APIs used)
// ============================================================
static cudaStream_t s1;
static cudaEvent_t evFork, evPH1, evC0, evC1, evJoin;
struct _GInit {
    _GInit() {
        cudaStreamCreateWithFlags(&s1, cudaStreamNonBlocking);
        cudaEventCreateWithFlags(&evFork, cudaEventDisableTiming);
        cudaEventCreateWithFlags(&evPH1, cudaEventDisableTiming);
        cudaEventCreateWithFlags(&evC0,  cudaEventDisableTiming);
        cudaEventCreateWithFlags(&evC1,  cudaEventDisableTiming);
        cudaEventCreateWithFlags(&evJoin, cudaEventDisableTiming);
    }
};
static _GInit _ginit;

// ============================================================
// launch: forked two-stream pipeline over batch halves
// s0: projH0, gateH0, c_updH0, c_updH1
// s1: projH1 || c_updH0 ; outprojH0 || c_updH1 ; outprojH1 tail
// ============================================================
extern "C" void kernel_launch(void* const* d_in, const int* in_sizes, int n_in,
                              void* d_out, int out_size)
{
    const float* x     = (const float*)d_in[0];
    const float* Cprev = (const float*)d_in[1];
    const float* nprev = (const float*)d_in[2];
    const float* mprev = (const float*)d_in[3];
    const float* Wq    = (const float*)d_in[4];
    const float* Wk    = (const float*)d_in[5];
    const float* Wv    = (const float*)d_in[6];
    const float* wi    = (const float*)d_in[7];
    const float* wib   = (const float*)d_in[8];
    const float* wf    = (const float*)d_in[9];
    const float* wfb   = (const float*)d_in[10];
    const float* Wo    = (const float*)d_in[11];
    const float* Wob   = (const float*)d_in[12];
    const float* P     = (const float*)d_in[13];

    float* out   = (float*)d_out;
    float* out_h = out;                                        // (B, 1024)
    float* out_c = out + (size_t)BATCH * DM;                   // (B, 1024, 1024)
    float* out_n = out_c + (size_t)BATCH * DH * DH;            // (B, 1024)
    float* out_m = out_n + (size_t)BATCH * DH;                 // (B,)

    // ---- s0: half 0 front-end ----
    proj_kernel<<<dim3(32, 1, 4), 128>>>(x, Wq, Wk, Wv, Wo, Wob, 0);
    gate_ndenom_kernel<<<64, 256>>>(x, wi, wib, wf, wfb, mprev, nprev, out_m, out_n, 0);
    cudaEventRecord(evFork, 0);

    // ---- s1: half 1 front-end (overlaps c_updH0) ----
    cudaStreamWaitEvent(s1, evFork, 0);
    proj_kernel<<<dim3(32, 1, 4), 128, 0, s1>>>(x, Wq, Wk, Wv, Wo, Wob, 64);
    gate_ndenom_kernel<<<64, 256, 0, s1>>>(x, wi, wib, wf, wfb, mprev, nprev, out_m, out_n, 64);
    cudaEventRecord(evPH1, s1);

    // ---- s0: DRAM-bound C updates ----
    c_update_kernel<<<dim3(64, 64), 512>>>(Cprev, out_c, 0);
    cudaEventRecord(evC0, 0);
    cudaStreamWaitEvent(0, evPH1, 0);
    c_update_kernel<<<dim3(64, 64), 512>>>(Cprev, out_c, 64);
    cudaEventRecord(evC1, 0);

    // ---- s1: out_proj halves (H0 overlaps c_updH1) ----
    cudaStreamWaitEvent(s1, evC0, 0);
    outproj_kernel<<<dim3(32, 1, 4), 128, 0, s1>>>(P, 0);
    outproj_reduce_kernel<<<64, 256, 0, s1>>>(out_h, 0);
    cudaStreamWaitEvent(s1, evC1, 0);
    outproj_kernel<<<dim3(32, 1, 4), 128, 0, s1>>>(P, 64);
    outproj_reduce_kernel<<<64, 256, 0, s1>>>(out_h, 64);
    cudaEventRecord(evJoin, s1);

    // ---- join back to capture stream ----
    cudaStreamWaitEvent(0, evJoin, 0);
}

// round 8
// speedup vs baseline: 1.1842x; 1.1842x over previous
#include <cuda_runtime.h>
#include <math.h>

#define DH 1024
#define DM 1024
#define BATCH 128
static constexpr float QK_SCALE = 0.03125f; // 1/sqrt(1024)

// -------- scratch (no allocations allowed) --------
__device__ float g_q[BATCH * DH];
__device__ float g_k[BATCH * DH];
__device__ float g_v[BATCH * DH];
__device__ float g_o[BATCH * DH];
__device__ float g_hh[BATCH * DH];
__device__ float g_part[8][BATCH * DM];   // split-K partials for out_proj
__device__ float g_ip[BATCH];
__device__ float g_fp[BATCH];
__device__ float g_den[BATCH];

__device__ __forceinline__ float warp_sum(float v) {
    #pragma unroll
    for (int s = 16; s; s >>= 1) v += __shfl_xor_sync(0xffffffffu, v, s);
    return v;
}

// ============================================================
// Projections q/k/v/sigmoid(o)
// BM=64, BN=32, BK=16, 128 threads, 4x4 thread tile.
// grid = (32 n-tiles, 2 m-tiles, 4 matrices) = 256 blocks.
// ============================================================
#define SMS 68  // smem row stride in floats

__global__ void __launch_bounds__(128)
proj_kernel(const float* __restrict__ x,
            const float* __restrict__ Wq, const float* __restrict__ Wk,
            const float* __restrict__ Wv, const float* __restrict__ Wo,
            const float* __restrict__ Wob)
{
    __shared__ float Xs[2][16][SMS];      // 64 m-rows
    __shared__ float Ws[2][16][36];       // 32 n-rows

    const int z = blockIdx.z;
    const float* __restrict__ W = (z == 0) ? Wq : (z == 1) ? Wk : (z == 2) ? Wv : Wo;
    float* __restrict__ Y = (z == 0) ? g_q : (z == 1) ? g_k : (z == 2) ? g_v : g_o;

    const int m0 = blockIdx.y * 64;
    const int n0 = blockIdx.x * 32;
    const int tid = threadIdx.x;
    const int tx = tid & 7;               // n frag
    const int ty = tid >> 3;              // m frag

    const int xr = tid >> 1;              // 0..63
    const int xc = tid & 1;               // 0..1
    const int wr = tid >> 2;              // 0..31
    const int wc = tid & 3;               // 0..3

    const float* __restrict__ xg = x + (size_t)(m0 + xr) * DM + xc * 8;
    const float* __restrict__ wg = W + (size_t)(n0 + wr) * DM + wc * 4;

    float4 xv0 = *(const float4*)xg;
    float4 xv1 = *(const float4*)(xg + 4);
    float4 wv  = *(const float4*)wg;

    float acc[4][4] = {};
    int buf = 0;

    #pragma unroll 1
    for (int kt = 0; kt < 64; kt++) {
        {
            const int cb = xc * 8;
            Xs[buf][cb + 0][xr] = xv0.x; Xs[buf][cb + 1][xr] = xv0.y;
            Xs[buf][cb + 2][xr] = xv0.z; Xs[buf][cb + 3][xr] = xv0.w;
            Xs[buf][cb + 4][xr] = xv1.x; Xs[buf][cb + 5][xr] = xv1.y;
            Xs[buf][cb + 6][xr] = xv1.z; Xs[buf][cb + 7][xr] = xv1.w;
            Ws[buf][wc * 4 + 0][wr] = wv.x; Ws[buf][wc * 4 + 1][wr] = wv.y;
            Ws[buf][wc * 4 + 2][wr] = wv.z; Ws[buf][wc * 4 + 3][wr] = wv.w;
        }
        __syncthreads();
        if (kt + 1 < 64) {
            xv0 = *(const float4*)(xg + (kt + 1) * 16);
            xv1 = *(const float4*)(xg + (kt + 1) * 16 + 4);
            wv  = *(const float4*)(wg + (kt + 1) * 16);
        }
        #pragma unroll
        for (int k = 0; k < 16; k++) {
            const float4 a = *(const float4*)&Xs[buf][k][ty * 4];
            const float4 w = *(const float4*)&Ws[buf][k][tx * 4];
            acc[0][0] = fmaf(a.x, w.x, acc[0][0]); acc[0][1] = fmaf(a.x, w.y, acc[0][1]);
            acc[0][2] = fmaf(a.x, w.z, acc[0][2]); acc[0][3] = fmaf(a.x, w.w, acc[0][3]);
            acc[1][0] = fmaf(a.y, w.x, acc[1][0]); acc[1][1] = fmaf(a.y, w.y, acc[1][1]);
            acc[1][2] = fmaf(a.y, w.z, acc[1][2]); acc[1][3] = fmaf(a.y, w.w, acc[1][3]);
            acc[2][0] = fmaf(a.z, w.x, acc[2][0]); acc[2][1] = fmaf(a.z, w.y, acc[2][1]);
            acc[2][2] = fmaf(a.z, w.z, acc[2][2]); acc[2][3] = fmaf(a.z, w.w, acc[2][3]);
            acc[3][0] = fmaf(a.w, w.x, acc[3][0]); acc[3][1] = fmaf(a.w, w.y, acc[3][1]);
            acc[3][2] = fmaf(a.w, w.z, acc[3][2]); acc[3][3] = fmaf(a.w, w.w, acc[3][3]);
        }
        __syncthreads();
        buf ^= 1;
    }

    #pragma unroll
    for (int i = 0; i < 4; i++) {
        const int m = m0 + ty * 4 + i;
        const int nb = n0 + tx * 4;
        float4 y;
        if (z == 3) {
            y.x = 1.f / (1.f + expf(-(acc[i][0] + Wob[nb + 0])));
            y.y = 1.f / (1.f + expf(-(acc[i][1] + Wob[nb + 1])));
            y.z = 1.f / (1.f + expf(-(acc[i][2] + Wob[nb + 2])));
            y.w = 1.f / (1.f + expf(-(acc[i][3] + Wob[nb + 3])));
        } else if (z == 2) {
            y.x = acc[i][0]; y.y = acc[i][1]; y.z = acc[i][2]; y.w = acc[i][3];
        } else {
            y.x = acc[i][0] * QK_SCALE; y.y = acc[i][1] * QK_SCALE;
            y.z = acc[i][2] * QK_SCALE; y.w = acc[i][3] * QK_SCALE;
        }
        *(float4*)&Y[(size_t)m * DH + nb] = y;
    }
}

// ============================================================
// Merged gating + n_t + denom (one block per batch, 256 thr)
// ============================================================
__global__ void __launch_bounds__(256)
gate_ndenom_kernel(const float* __restrict__ x,
                   const float* __restrict__ wi, const float* __restrict__ wib,
                   const float* __restrict__ wf, const float* __restrict__ wfb,
                   const float* __restrict__ mprev,
                   const float* __restrict__ nprev,
                   float* __restrict__ out_m, float* __restrict__ out_n)
{
    const int b = blockIdx.x;
    const int t = threadIdx.x;

    const float4 xv = ((const float4*)(x + (size_t)b * DM))[t];
    const float4 iv = ((const float4*)wi)[t];
    const float4 fv = ((const float4*)wf)[t];
    float si = xv.x * iv.x + xv.y * iv.y + xv.z * iv.z + xv.w * iv.w;
    float sf = xv.x * fv.x + xv.y * fv.y + xv.z * fv.z + xv.w * fv.w;

    __shared__ float sbi[8], sbf[8], sgate[2];
    si = warp_sum(si); sf = warp_sum(sf);
    if ((t & 31) == 0) { sbi[t >> 5] = si; sbf[t >> 5] = sf; }
    __syncthreads();
    if (t == 0) {
        float zi = 0.f, zf = 0.f;
        #pragma unroll
        for (int w = 0; w < 8; w++) { zi += sbi[w]; zf += sbf[w]; }
        zi += *wib; zf += *wfb;
        const float mp = mprev[b];
        const float mt = fmaxf(zf + mp, zi);
        const float ip = expf(zi - mt);
        const float fp = expf(zf + mp - mt);
        out_m[b] = mt;
        g_ip[b] = ip; g_fp[b] = fp;
        sgate[0] = ip; sgate[1] = fp;
    }
    __syncthreads();

    const float ip = sgate[0];
    const float f  = sgate[1];
    const float4 np = ((const float4*)(nprev + (size_t)b * DH))[t];
    const float4 kv = ((const float4*)(g_k   + (size_t)b * DH))[t];
    const float4 qv = ((const float4*)(g_q   + (size_t)b * DH))[t];
    float4 n;
    n.x = f * np.x + ip * kv.x;
    n.y = f * np.y + ip * kv.y;
    n.z = f * np.z + ip * kv.z;
    n.w = f * np.w + ip * kv.w;
    ((float4*)(out_n + (size_t)b * DH))[t] = n;

    float s = n.x * qv.x + n.y * qv.y + n.z * qv.z + n.w * qv.w;
    s = warp_sum(s);
    if ((t & 31) == 0) sbi[t >> 5] = s;
    __syncthreads();
    if (t == 0) {
        float tot = 0.f;
        #pragma unroll
        for (int w = 0; w < 8; w++) tot += sbi[w];
        g_den[b] = fmaxf(fabsf(tot), 1.f);
    }
}

// ============================================================
// Fused C update + Cq matvec + h_head  (HBM-bound)
// grid (64 row-chunks, 128 batches), 512 threads = 16 warps.
// ============================================================
__global__ void __launch_bounds__(512)
c_update_kernel(const float* __restrict__ Cprev, float* __restrict__ Cout)
{
    const int b = blockIdx.y;
    __shared__ float4 ks4[256];
    __shared__ float4 qs4[256];
    if (threadIdx.x < 256) {
        const int t = threadIdx.x;
        ks4[t] = ((const float4*)(g_k + (size_t)b * DH))[t];
        qs4[t] = ((const float4*)(g_q + (size_t)b * DH))[t];
    }
    __syncthreads();

    const int warp = threadIdx.x >> 5;
    const int lane = threadIdx.x & 31;
    const int i = blockIdx.x * 16 + warp;

    const float f  = g_fp[b];
    const float iv = g_ip[b] * g_v[(size_t)b * DH + i];

    const float4* __restrict__ cp = (const float4*)(Cprev + ((size_t)b * DH + i) * DH);
    float4* __restrict__ co = (float4*)(Cout + ((size_t)b * DH + i) * DH);

    float4 c[8];
    #pragma unroll
    for (int u = 0; u < 8; u++) c[u] = __ldcs(&cp[u * 32 + lane]);

    float acc = 0.f;
    #pragma unroll
    for (int u = 0; u < 8; u++) {
        const int j4 = u * 32 + lane;
        const float4 k4 = ks4[j4];
        const float4 q4 = qs4[j4];
        float4 o;
        o.x = fmaf(f, c[u].x, iv * k4.x);
        o.y = fmaf(f, c[u].y, iv * k4.y);
        o.z = fmaf(f, c[u].z, iv * k4.z);
        o.w = fmaf(f, c[u].w, iv * k4.w);
        acc = fmaf(o.x, q4.x, acc);
        acc = fmaf(o.y, q4.y, acc);
        acc = fmaf(o.z, q4.z, acc);
        acc = fmaf(o.w, q4.w, acc);
        __stcs(&co[j4], o);
    }
    acc = warp_sum(acc);
    if (lane == 0)
        g_hh[(size_t)b * DH + i] = g_o[(size_t)b * DH + i] * acc / g_den[b];
}

// ============================================================
// out_proj split-K=8: grid (32 n, 2 m, 8 ksplit) = 512 blocks
// BM=64, BN=32, BK=16, 4x4 tile, K-range 128 per split
// ============================================================
__global__ void __launch_bounds__(128)
outproj_kernel(const float* __restrict__ P)
{
    __shared__ float Xs[2][16][SMS];
    __shared__ float Ws[2][16][36];

    const int z  = blockIdx.z;
    const int m0 = blockIdx.y * 64;
    const int n0 = blockIdx.x * 32;
    const int tid = threadIdx.x;
    const int tx = tid & 7;
    const int ty = tid >> 3;

    const int xr = tid >> 1, xc = tid & 1;
    const int wr = tid >> 2, wc = tid & 3;
    const int kbeg = z * 128;

    const float* __restrict__ xg = g_hh + (size_t)(m0 + xr) * DH + kbeg + xc * 8;
    const float* __restrict__ wg = P    + (size_t)(n0 + wr) * DH + kbeg + wc * 4;

    float4 xv0 = *(const float4*)xg;
    float4 xv1 = *(const float4*)(xg + 4);
    float4 wv  = *(const float4*)wg;

    float acc[4][4] = {};
    int buf = 0;

    #pragma unroll 1
    for (int kt = 0; kt < 8; kt++) {
        {
            const int cb = xc * 8;
            Xs[buf][cb + 0][xr] = xv0.x; Xs[buf][cb + 1][xr] = xv0.y;
            Xs[buf][cb + 2][xr] = xv0.z; Xs[buf][cb + 3][xr] = xv0.w;
            Xs[buf][cb + 4][xr] = xv1.x; Xs[buf][cb + 5][xr] = xv1.y;
            Xs[buf][cb + 6][xr] = xv1.z; Xs[buf][cb + 7][xr] = xv1.w;
            Ws[buf][wc * 4 + 0][wr] = wv.x; Ws[buf][wc * 4 + 1][wr] = wv.y;
            Ws[buf][wc * 4 + 2][wr] = wv.z; Ws[buf][wc * 4 + 3][wr] = wv.w;
        }
        __syncthreads();
        if (kt + 1 < 8) {
            xv0 = *(const float4*)(xg + (kt + 1) * 16);
            xv1 = *(const float4*)(xg + (kt + 1) * 16 + 4);
            wv  = *(const float4*)(wg + (kt + 1) * 16);
        }
        #pragma unroll
        for (int k = 0; k < 16; k++) {
            const float4 a = *(const float4*)&Xs[buf][k][ty * 4];
            const float4 w = *(const float4*)&Ws[buf][k][tx * 4];
            acc[0][0] = fmaf(a.x, w.x, acc[0][0]); acc[0][1] = fmaf(a.x, w.y, acc[0][1]);
            acc[0][2] = fmaf(a.x, w.z, acc[0][2]); acc[0][3] = fmaf(a.x, w.w, acc[0][3]);
            acc[1][0] = fmaf(a.y, w.x, acc[1][0]); acc[1][1] = fmaf(a.y, w.y, acc[1][1]);
            acc[1][2] = fmaf(a.y, w.z, acc[1][2]); acc[1][3] = fmaf(a.y, w.w, acc[1][3]);
            acc[2][0] = fmaf(a.z, w.x, acc[2][0]); acc[2][1] = fmaf(a.z, w.y, acc[2][1]);
            acc[2][2] = fmaf(a.z, w.z, acc[2][2]); acc[2][3] = fmaf(a.z, w.w, acc[2][3]);
            acc[3][0] = fmaf(a.w, w.x, acc[3][0]); acc[3][1] = fmaf(a.w, w.y, acc[3][1]);
            acc[3][2] = fmaf(a.w, w.z, acc[3][2]); acc[3][3] = fmaf(a.w, w.w, acc[3][3]);
        }
        __syncthreads();
        buf ^= 1;
    }

    float* __restrict__ Yp = g_part[z];
    #pragma unroll
    for (int i = 0; i < 4; i++) {
        const int m = m0 + ty * 4 + i;
        const int nb = n0 + tx * 4;
        float4 y;
        y.x = acc[i][0]; y.y = acc[i][1]; y.z = acc[i][2]; y.w = acc[i][3];
        *(float4*)&Yp[(size_t)m * DM + nb] = y;
    }
}

__global__ void __launch_bounds__(256)
outproj_reduce_kernel(float* __restrict__ out_h)
{
    const int idx = blockIdx.x * 256 + threadIdx.x; // float4 index
    float4 r = {0.f, 0.f, 0.f, 0.f};
    #pragma unroll
    for (int p = 0; p < 8; p++) {
        const float4 a = ((const float4*)g_part[p])[idx];
        r.x += a.x; r.y += a.y; r.z += a.z; r.w += a.w;
    }
    ((float4*)out_h)[idx] = r;
}

// ============================================================
// launch (serial single-stream — overlap measured net-negative)
// ============================================================
extern "C" void kernel_launch(void* const* d_in, const int* in_sizes, int n_in,
                              void* d_out, int out_size)
{
    const float* x     = (const float*)d_in[0];
    const float* Cprev = (const float*)d_in[1];
    const float* nprev = (const float*)d_in[2];
    const float* mprev = (const float*)d_in[3];
    const float* Wq    = (const float*)d_in[4];
    const float* Wk    = (const float*)d_in[5];
    const float* Wv    = (const float*)d_in[6];
    const float* wi    = (const float*)d_in[7];
    const float* wib   = (const float*)d_in[8];
    const float* wf    = (const float*)d_in[9];
    const float* wfb   = (const float*)d_in[10];
    const float* Wo    = (const float*)d_in[11];
    const float* Wob   = (const float*)d_in[12];
    const float* P     = (const float*)d_in[13];

    float* out   = (float*)d_out;
    float* out_h = out;                                        // (B, 1024)
    float* out_c = out + (size_t)BATCH * DM;                   // (B, 1024, 1024)
    float* out_n = out_c + (size_t)BATCH * DH * DH;            // (B, 1024)
    float* out_m = out_n + (size_t)BATCH * DH;                 // (B,)

    proj_kernel<<<dim3(32, 2, 4), 128>>>(x, Wq, Wk, Wv, Wo, Wob);
    gate_ndenom_kernel<<<BATCH, 256>>>(x, wi, wib, wf, wfb, mprev, nprev, out_m, out_n);
    c_update_kernel<<<dim3(64, BATCH), 512>>>(Cprev, out_c);
    outproj_kernel<<<dim3(32, 2, 8), 128>>>(P);
    outproj_reduce_kernel<<<128, 256>>>(out_h);
}

// round 9
// speedup vs baseline: 1.2415x; 1.0484x over previous
#include <cuda_runtime.h>
#include <cuda_bf16.h>
#include <mma.h>
#include <math.h>

using namespace nvcuda;

#define DH 1024
#define DM 1024
#define BATCH 128
static constexpr float QK_SCALE = 0.03125f; // 1/sqrt(1024)

// -------- scratch (no allocations allowed) --------
__device__ float g_q[BATCH * DH];
__device__ float g_k[BATCH * DH];
__device__ float g_v[BATCH * DH];
__device__ float g_o[BATCH * DH];
__device__ float g_hh[BATCH * DH];
__device__ float g_part[4][BATCH * DM];   // split-K partials for out_proj
__device__ float g_ip[BATCH];
__device__ float g_fp[BATCH];
__device__ float g_den[BATCH];

__device__ __forceinline__ float warp_sum(float v) {
    #pragma unroll
    for (int s = 16; s; s >>= 1) v += __shfl_xor_sync(0xffffffffu, v, s);
    return v;
}

// ============================================================
// Split-bf16 WMMA GEMM core.
// Computes acc[2] (two 16x16 tiles) for a 64x64 output block:
//   Y[m,n] = sum_k X[m,k] * W[n,k]
// X,W fp32 row-major; per 32-wide k-chunk both are split into
// bf16 hi/lo in smem; 3 MMAs (hh, hl, lh) per tile per k-step.
// 256 threads = 8 warps: warp_m = w>>1 (16 rows), warp_n = w&1 (32 cols).
// ============================================================
#define KCH 32          // k-chunk width
#define BLD 40          // bf16 smem row stride (multiple of 8)

struct GemmSmem {
    __nv_bfloat16 XH[64][BLD];
    __nv_bfloat16 XL[64][BLD];
    __nv_bfloat16 WH[64][BLD];
    __nv_bfloat16 WL[64][BLD];
    float YS[64][72];
};

__device__ __forceinline__ void split_store(
    __nv_bfloat16 (&H)[64][BLD], __nv_bfloat16 (&L)[64][BLD],
    int r, int c, float4 v)
{
    __nv_bfloat16 hx = __float2bfloat16(v.x);
    __nv_bfloat16 hy = __float2bfloat16(v.y);
    __nv_bfloat16 hz = __float2bfloat16(v.z);
    __nv_bfloat16 hw = __float2bfloat16(v.w);
    __nv_bfloat16 lx = __float2bfloat16(v.x - __bfloat162float(hx));
    __nv_bfloat16 ly = __float2bfloat16(v.y - __bfloat162float(hy));
    __nv_bfloat16 lz = __float2bfloat16(v.z - __bfloat162float(hz));
    __nv_bfloat16 lw = __float2bfloat16(v.w - __bfloat162float(hw));
    *(__nv_bfloat162*)&H[r][c]     = __nv_bfloat162(hx, hy);
    *(__nv_bfloat162*)&H[r][c + 2] = __nv_bfloat162(hz, hw);
    *(__nv_bfloat162*)&L[r][c]     = __nv_bfloat162(lx, ly);
    *(__nv_bfloat162*)&L[r][c + 2] = __nv_bfloat162(lz, lw);
}

// X at (m0, kbeg), W at (n0, kbeg); nchunks k-chunks of 32.
// Result left in s.YS[64][72] (all 8 warps' tiles). Caller syncs after.
__device__ __forceinline__ void gemm_wmma(
    GemmSmem& s, const float* __restrict__ X, const float* __restrict__ W,
    int m0, int n0, int kbeg, int nchunks)
{
    const int tid  = threadIdx.x;
    const int warp = tid >> 5;
    const int wm   = warp >> 1;   // 0..3 -> m tile (16 rows)
    const int wn   = warp & 1;    // 0..1 -> n half (32 cols)

    wmma::fragment<wmma::accumulator, 16, 16, 16, float> acc[2];
    wmma::fill_fragment(acc[0], 0.f);
    wmma::fill_fragment(acc[1], 0.f);

    // loader geometry: 512 float4 per tile, 2 per thread
    const int r0 = tid >> 3;                 // 0..31
    const int c0 = (tid & 7) * 4;            // 0,4,..28
    const float* __restrict__ xg = X + (size_t)(m0 + r0) * DM + kbeg + c0;
    const float* __restrict__ wg = W + (size_t)(n0 + r0) * DM + kbeg + c0;
    // second element: rows 32..63
    const float* __restrict__ xg2 = xg + 32 * DM;
    const float* __restrict__ wg2 = wg + 32 * DM;

    float4 px0 = *(const float4*)xg;
    float4 px1 = *(const float4*)xg2;
    float4 pw0 = *(const float4*)wg;
    float4 pw1 = *(const float4*)wg2;

    for (int kc = 0; kc < nchunks; kc++) {
        split_store(s.XH, s.XL, r0,      c0, px0);
        split_store(s.XH, s.XL, r0 + 32, c0, px1);
        split_store(s.WH, s.WL, r0,      c0, pw0);
        split_store(s.WH, s.WL, r0 + 32, c0, pw1);
        __syncthreads();

        if (kc + 1 < nchunks) {
            px0 = *(const float4*)(xg  + (kc + 1) * KCH);
            px1 = *(const float4*)(xg2 + (kc + 1) * KCH);
            pw0 = *(const float4*)(wg  + (kc + 1) * KCH);
            pw1 = *(const float4*)(wg2 + (kc + 1) * KCH);
        }

        #pragma unroll
        for (int ks = 0; ks < KCH; ks += 16) {
            wmma::fragment<wmma::matrix_a, 16, 16, 16, __nv_bfloat16, wmma::row_major> ah, al;
            wmma::load_matrix_sync(ah, &s.XH[wm * 16][ks], BLD);
            wmma::load_matrix_sync(al, &s.XL[wm * 16][ks], BLD);
            #pragma unroll
            for (int t = 0; t < 2; t++) {
                wmma::fragment<wmma::matrix_b, 16, 16, 16, __nv_bfloat16, wmma::col_major> bh, bl;
                wmma::load_matrix_sync(bh, &s.WH[wn * 32 + t * 16][ks], BLD);
                wmma::load_matrix_sync(bl, &s.WL[wn * 32 + t * 16][ks], BLD);
                wmma::mma_sync(acc[t], ah, bh, acc[t]);
                wmma::mma_sync(acc[t], ah, bl, acc[t]);
                wmma::mma_sync(acc[t], al, bh, acc[t]);
            }
        }
        __syncthreads();
    }

    wmma::store_matrix_sync(&s.YS[wm * 16][wn * 32],      acc[0], 72, wmma::mem_row_major);
    wmma::store_matrix_sync(&s.YS[wm * 16][wn * 32 + 16], acc[1], 72, wmma::mem_row_major);
}

// ============================================================
// Projections q/k/v/sigmoid(o): grid (16 n, 2 m, 4 mat), 256 thr
// ============================================================
__global__ void __launch_bounds__(256)
proj_kernel(const float* __restrict__ x,
            const float* __restrict__ Wq, const float* __restrict__ Wk,
            const float* __restrict__ Wv, const float* __restrict__ Wo,
            const float* __restrict__ Wob)
{
    __shared__ GemmSmem s;

    const int z = blockIdx.z;
    const float* __restrict__ W = (z == 0) ? Wq : (z == 1) ? Wk : (z == 2) ? Wv : Wo;
    float* __restrict__ Y = (z == 0) ? g_q : (z == 1) ? g_k : (z == 2) ? g_v : g_o;

    const int m0 = blockIdx.y * 64;
    const int n0 = blockIdx.x * 64;

    gemm_wmma(s, x, W, m0, n0, 0, DM / KCH);
    __syncthreads();

    const int tid = threadIdx.x;
    #pragma unroll
    for (int ii = 0; ii < 4; ii++) {
        const int idx = tid + ii * 256;       // 0..1023 float4 slots
        const int r = idx >> 4;               // 0..63
        const int c = (idx & 15) * 4;         // 0..60
        float4 v = *(const float4*)&s.YS[r][c];
        const int n = n0 + c;
        if (z == 3) {
            v.x = 1.f / (1.f + expf(-(v.x + Wob[n + 0])));
            v.y = 1.f / (1.f + expf(-(v.y + Wob[n + 1])));
            v.z = 1.f / (1.f + expf(-(v.z + Wob[n + 2])));
            v.w = 1.f / (1.f + expf(-(v.w + Wob[n + 3])));
        } else if (z != 2) {
            v.x *= QK_SCALE; v.y *= QK_SCALE; v.z *= QK_SCALE; v.w *= QK_SCALE;
        }
        *(float4*)&Y[(size_t)(m0 + r) * DH + n] = v;
    }
}

// ============================================================
// out_proj: split-K=4 wmma -> partials, grid (16 n, 2 m, 4 kz)
// ============================================================
__global__ void __launch_bounds__(256)
outproj_kernel(const float* __restrict__ P)
{
    __shared__ GemmSmem s;

    const int z  = blockIdx.z;
    const int m0 = blockIdx.y * 64;
    const int n0 = blockIdx.x * 64;

    gemm_wmma(s, g_hh, P, m0, n0, z * 256, 256 / KCH);
    __syncthreads();

    float* __restrict__ Yp = g_part[z];
    const int tid = threadIdx.x;
    #pragma unroll
    for (int ii = 0; ii < 4; ii++) {
        const int idx = tid + ii * 256;
        const int r = idx >> 4;
        const int c = (idx & 15) * 4;
        const float4 v = *(const float4*)&s.YS[r][c];
        *(float4*)&Yp[(size_t)(m0 + r) * DM + n0 + c] = v;
    }
}

__global__ void __launch_bounds__(256)
outproj_reduce_kernel(float* __restrict__ out_h)
{
    const int idx = blockIdx.x * 256 + threadIdx.x; // float4 index
    const float4 a = ((const float4*)g_part[0])[idx];
    const float4 b = ((const float4*)g_part[1])[idx];
    const float4 c = ((const float4*)g_part[2])[idx];
    const float4 d = ((const float4*)g_part[3])[idx];
    float4 r;
    r.x = (a.x + b.x) + (c.x + d.x);
    r.y = (a.y + b.y) + (c.y + d.y);
    r.z = (a.z + b.z) + (c.z + d.z);
    r.w = (a.w + b.w) + (c.w + d.w);
    ((float4*)out_h)[idx] = r;
}

// ============================================================
// Merged gating + n_t + denom (one block per batch, 256 thr)
// ============================================================
__global__ void __launch_bounds__(256)
gate_ndenom_kernel(const float* __restrict__ x,
                   const float* __restrict__ wi, const float* __restrict__ wib,
                   const float* __restrict__ wf, const float* __restrict__ wfb,
                   const float* __restrict__ mprev,
                   const float* __restrict__ nprev,
                   float* __restrict__ out_m, float* __restrict__ out_n)
{
    const int b = blockIdx.x;
    const int t = threadIdx.x;

    const float4 xv = ((const float4*)(x + (size_t)b * DM))[t];
    const float4 iv = ((const float4*)wi)[t];
    const float4 fv = ((const float4*)wf)[t];
    float si = xv.x * iv.x + xv.y * iv.y + xv.z * iv.z + xv.w * iv.w;
    float sf = xv.x * fv.x + xv.y * fv.y + xv.z * fv.z + xv.w * fv.w;

    __shared__ float sbi[8], sbf[8], sgate[2];
    si = warp_sum(si); sf = warp_sum(sf);
    if ((t & 31) == 0) { sbi[t >> 5] = si; sbf[t >> 5] = sf; }
    __syncthreads();
    if (t == 0) {
        float zi = 0.f, zf = 0.f;
        #pragma unroll
        for (int w = 0; w < 8; w++) { zi += sbi[w]; zf += sbf[w]; }
        zi += *wib; zf += *wfb;
        const float mp = mprev[b];
        const float mt = fmaxf(zf + mp, zi);
        const float ip = expf(zi - mt);
        const float fp = expf(zf + mp - mt);
        out_m[b] = mt;
        g_ip[b] = ip; g_fp[b] = fp;
        sgate[0] = ip; sgate[1] = fp;
    }
    __syncthreads();

    const float ip = sgate[0];
    const float f  = sgate[1];
    const float4 np = ((const float4*)(nprev + (size_t)b * DH))[t];
    const float4 kv = ((const float4*)(g_k   + (size_t)b * DH))[t];
    const float4 qv = ((const float4*)(g_q   + (size_t)b * DH))[t];
    float4 n;
    n.x = f * np.x + ip * kv.x;
    n.y = f * np.y + ip * kv.y;
    n.z = f * np.z + ip * kv.z;
    n.w = f * np.w + ip * kv.w;
    ((float4*)(out_n + (size_t)b * DH))[t] = n;

    float s = n.x * qv.x + n.y * qv.y + n.z * qv.z + n.w * qv.w;
    s = warp_sum(s);
    if ((t & 31) == 0) sbi[t >> 5] = s;
    __syncthreads();
    if (t == 0) {
        float tot = 0.f;
        #pragma unroll
        for (int w = 0; w < 8; w++) tot += sbi[w];
        g_den[b] = fmaxf(fabsf(tot), 1.f);
    }
}

// ============================================================
// Fused C update + Cq matvec + h_head  (HBM-bound)
// grid (64 row-chunks, 128 batches), 512 threads = 16 warps.
// ============================================================
__global__ void __launch_bounds__(512)
c_update_kernel(const float* __restrict__ Cprev, float* __restrict__ Cout)
{
    const int b = blockIdx.y;
    __shared__ float4 ks4[256];
    __shared__ float4 qs4[256];
    if (threadIdx.x < 256) {
        const int t = threadIdx.x;
        ks4[t] = ((const float4*)(g_k + (size_t)b * DH))[t];
        qs4[t] = ((const float4*)(g_q + (size_t)b * DH))[t];
    }
    __syncthreads();

    const int warp = threadIdx.x >> 5;
    const int lane = threadIdx.x & 31;
    const int i = blockIdx.x * 16 + warp;

    const float f  = g_fp[b];
    const float iv = g_ip[b] * g_v[(size_t)b * DH + i];

    const float4* __restrict__ cp = (const float4*)(Cprev + ((size_t)b * DH + i) * DH);
    float4* __restrict__ co = (float4*)(Cout + ((size_t)b * DH + i) * DH);

    float4 c[8];
    #pragma unroll
    for (int u = 0; u < 8; u++) c[u] = __ldcs(&cp[u * 32 + lane]);

    float acc = 0.f;
    #pragma unroll
    for (int u = 0; u < 8; u++) {
        const int j4 = u * 32 + lane;
        const float4 k4 = ks4[j4];
        const float4 q4 = qs4[j4];
        float4 o;
        o.x = fmaf(f, c[u].x, iv * k4.x);
        o.y = fmaf(f, c[u].y, iv * k4.y);
        o.z = fmaf(f, c[u].z, iv * k4.z);
        o.w = fmaf(f, c[u].w, iv * k4.w);
        acc = fmaf(o.x, q4.x, acc);
        acc = fmaf(o.y, q4.y, acc);
        acc = fmaf(o.z, q4.z, acc);
        acc = fmaf(o.w, q4.w, acc);
        __stcs(&co[j4], o);
    }
    acc = warp_sum(acc);
    if (lane == 0)
        g_hh[(size_t)b * DH + i] = g_o[(size_t)b * DH + i] * acc / g_den[b];
}

// ============================================================
// launch (serial single-stream)
// ============================================================
extern "C" void kernel_launch(void* const* d_in, const int* in_sizes, int n_in,
                              void* d_out, int out_size)
{
    const float* x     = (const float*)d_in[0];
    const float* Cprev = (const float*)d_in[1];
    const float* nprev = (const float*)d_in[2];
    const float* mprev = (const float*)d_in[3];
    const float* Wq    = (const float*)d_in[4];
    const float* Wk    = (const float*)d_in[5];
    const float* Wv    = (const float*)d_in[6];
    const float* wi    = (const float*)d_in[7];
    const float* wib   = (const float*)d_in[8];
    const float* wf    = (const float*)d_in[9];
    const float* wfb   = (const float*)d_in[10];
    const float* Wo    = (const float*)d_in[11];
    const float* Wob   = (const float*)d_in[12];
    const float* P     = (const float*)d_in[13];

    float* out   = (float*)d_out;
    float* out_h = out;                                        // (B, 1024)
    float* out_c = out + (size_t)BATCH * DM;                   // (B, 1024, 1024)
    float* out_n = out_c + (size_t)BATCH * DH * DH;            // (B, 1024)
    float* out_m = out_n + (size_t)BATCH * DH;                 // (B,)

    proj_kernel<<<dim3(16, 2, 4), 256>>>(x, Wq, Wk, Wv, Wo, Wob);
    gate_ndenom_kernel<<<BATCH, 256>>>(x, wi, wib, wf, wfb, mprev, nprev, out_m, out_n);
    c_update_kernel<<<dim3(64, BATCH), 512>>>(Cprev, out_c);
    outproj_kernel<<<dim3(16, 2, 4), 256>>>(P);
    outproj_reduce_kernel<<<128, 256>>>(out_h);
}

// round 10
// speedup vs baseline: 1.2672x; 1.0207x over previous
#include <cuda_runtime.h>
#include <cuda_bf16.h>
#include <mma.h>
#include <math.h>

using namespace nvcuda;

#define DH 1024
#define DM 1024
#define BATCH 128
static constexpr float QK_SCALE = 0.03125f; // 1/sqrt(1024)

// -------- scratch (no allocations allowed) --------
__device__ float g_q[BATCH * DH];
__device__ float g_k[BATCH * DH];
__device__ float g_v[BATCH * DH];
__device__ float g_o[BATCH * DH];
__device__ float g_hh[BATCH * DH];
__device__ float g_part[8][BATCH * DM];   // split-K partials for out_proj
__device__ float g_ip[BATCH];
__device__ float g_fp[BATCH];
__device__ float g_den[BATCH];

__device__ __forceinline__ float warp_sum(float v) {
    #pragma unroll
    for (int s = 16; s; s >>= 1) v += __shfl_xor_sync(0xffffffffu, v, s);
    return v;
}

// ============================================================
// Split-bf16 WMMA GEMM core, one-sync double-buffered pipeline.
//   Y[m,n] = sum_k X[m,k] * W[n,k]   (64x64 tile per block)
// Buffers: 2 x {XH, XL, WH, WL}[64][40] bf16 (20480 B each set).
// fp32 epilogue tile YS[64][72] overlaps buffer 0 (used only
// after the final MMA + sync).
// 256 threads = 8 warps: wm = warp>>1 (16 rows), wn = warp&1 (32 cols).
// ============================================================
#define KCH 32          // k-chunk width
#define BLD 40          // bf16 smem row stride
#define ARR_B (64 * BLD * 2)        // 5120 bytes per array
#define BUF_B (4 * ARR_B)           // 20480 bytes per buffer set

__device__ __forceinline__ __nv_bfloat16* sm_arr(char* raw, int buf, int arr) {
    return (__nv_bfloat16*)(raw + buf * BUF_B + arr * ARR_B);
}

__device__ __forceinline__ void split_store_row(
    __nv_bfloat16* H, __nv_bfloat16* L, int r, int c, float4 v)
{
    __nv_bfloat16 hx = __float2bfloat16(v.x);
    __nv_bfloat16 hy = __float2bfloat16(v.y);
    __nv_bfloat16 hz = __float2bfloat16(v.z);
    __nv_bfloat16 hw = __float2bfloat16(v.w);
    __nv_bfloat16 lx = __float2bfloat16(v.x - __bfloat162float(hx));
    __nv_bfloat16 ly = __float2bfloat16(v.y - __bfloat162float(hy));
    __nv_bfloat16 lz = __float2bfloat16(v.z - __bfloat162float(hz));
    __nv_bfloat16 lw = __float2bfloat16(v.w - __bfloat162float(hw));
    *(__nv_bfloat162*)&H[r * BLD + c]     = __nv_bfloat162(hx, hy);
    *(__nv_bfloat162*)&H[r * BLD + c + 2] = __nv_bfloat162(hz, hw);
    *(__nv_bfloat162*)&L[r * BLD + c]     = __nv_bfloat162(lx, ly);
    *(__nv_bfloat162*)&L[r * BLD + c + 2] = __nv_bfloat162(lz, lw);
}

// Runs the GEMM, leaves result in YS (= (float*)raw, stride 72).
// Caller must __syncthreads() after this returns before reading YS.
__device__ __forceinline__ void gemm_wmma(
    char* raw, const float* __restrict__ X, const float* __restrict__ W,
    int m0, int n0, int kbeg, int nchunks)
{
    const int tid  = threadIdx.x;
    const int warp = tid >> 5;
    const int wm   = warp >> 1;
    const int wn   = warp & 1;

    wmma::fragment<wmma::accumulator, 16, 16, 16, float> acc[2];
    wmma::fill_fragment(acc[0], 0.f);
    wmma::fill_fragment(acc[1], 0.f);

    const int r0 = tid >> 3;                 // 0..31
    const int c0 = (tid & 7) * 4;            // 0,4,..28
    const float* __restrict__ xg  = X + (size_t)(m0 + r0) * DM + kbeg + c0;
    const float* __restrict__ wg  = W + (size_t)(n0 + r0) * DM + kbeg + c0;
    const float* __restrict__ xg2 = xg + 32 * DM;
    const float* __restrict__ wg2 = wg + 32 * DM;

    float4 px0 = *(const float4*)xg;
    float4 px1 = *(const float4*)xg2;
    float4 pw0 = *(const float4*)wg;
    float4 pw1 = *(const float4*)wg2;

    // stage chunk 0 into buffer 0
    split_store_row(sm_arr(raw,0,0), sm_arr(raw,0,1), r0,      c0, px0);
    split_store_row(sm_arr(raw,0,0), sm_arr(raw,0,1), r0 + 32, c0, px1);
    split_store_row(sm_arr(raw,0,2), sm_arr(raw,0,3), r0,      c0, pw0);
    split_store_row(sm_arr(raw,0,2), sm_arr(raw,0,3), r0 + 32, c0, pw1);
    __syncthreads();

    for (int kc = 0; kc < nchunks; kc++) {
        const int b = kc & 1;
        if (kc + 1 < nchunks) {
            px0 = *(const float4*)(xg  + (kc + 1) * KCH);
            px1 = *(const float4*)(xg2 + (kc + 1) * KCH);
            pw0 = *(const float4*)(wg  + (kc + 1) * KCH);
            pw1 = *(const float4*)(wg2 + (kc + 1) * KCH);
        }

        const __nv_bfloat16* XH = sm_arr(raw, b, 0);
        const __nv_bfloat16* XL = sm_arr(raw, b, 1);
        const __nv_bfloat16* WH = sm_arr(raw, b, 2);
        const __nv_bfloat16* WL = sm_arr(raw, b, 3);

        #pragma unroll
        for (int ks = 0; ks < KCH; ks += 16) {
            wmma::fragment<wmma::matrix_a, 16, 16, 16, __nv_bfloat16, wmma::row_major> ah, al;
            wmma::load_matrix_sync(ah, &XH[(wm * 16) * BLD + ks], BLD);
            wmma::load_matrix_sync(al, &XL[(wm * 16) * BLD + ks], BLD);
            #pragma unroll
            for (int t = 0; t < 2; t++) {
                wmma::fragment<wmma::matrix_b, 16, 16, 16, __nv_bfloat16, wmma::col_major> bh, bl;
                wmma::load_matrix_sync(bh, &WH[(wn * 32 + t * 16) * BLD + ks], BLD);
                wmma::load_matrix_sync(bl, &WL[(wn * 32 + t * 16) * BLD + ks], BLD);
                wmma::mma_sync(acc[t], ah, bh, acc[t]);
                wmma::mma_sync(acc[t], ah, bl, acc[t]);
                wmma::mma_sync(acc[t], al, bh, acc[t]);
            }
        }

        if (kc + 1 < nchunks) {
            const int nb = b ^ 1;
            split_store_row(sm_arr(raw,nb,0), sm_arr(raw,nb,1), r0,      c0, px0);
            split_store_row(sm_arr(raw,nb,0), sm_arr(raw,nb,1), r0 + 32, c0, px1);
            split_store_row(sm_arr(raw,nb,2), sm_arr(raw,nb,3), r0,      c0, pw0);
            split_store_row(sm_arr(raw,nb,2), sm_arr(raw,nb,3), r0 + 32, c0, pw1);
            __syncthreads();
        }
    }

    __syncthreads();   // all MMAs done before YS (overlapping buf0) is written
    float* YS = (float*)raw;
    wmma::store_matrix_sync(&YS[(wm * 16) * 72 + wn * 32],      acc[0], 72, wmma::mem_row_major);
    wmma::store_matrix_sync(&YS[(wm * 16) * 72 + wn * 32 + 16], acc[1], 72, wmma::mem_row_major);
}

// ============================================================
// Projections q/k/v/sigmoid(o): grid (16 n, 2 m, 4 mat), 256 thr
// ============================================================
__global__ void __launch_bounds__(256)
proj_kernel(const float* __restrict__ x,
            const float* __restrict__ Wq, const float* __restrict__ Wk,
            const float* __restrict__ Wv, const float* __restrict__ Wo,
            const float* __restrict__ Wob)
{
    __shared__ __align__(16) char raw[2 * BUF_B];

    const int z = blockIdx.z;
    const float* __restrict__ W = (z == 0) ? Wq : (z == 1) ? Wk : (z == 2) ? Wv : Wo;
    float* __restrict__ Y = (z == 0) ? g_q : (z == 1) ? g_k : (z == 2) ? g_v : g_o;

    const int m0 = blockIdx.y * 64;
    const int n0 = blockIdx.x * 64;

    gemm_wmma(raw, x, W, m0, n0, 0, DM / KCH);
    __syncthreads();

    const float* YS = (const float*)raw;
    const int tid = threadIdx.x;
    #pragma unroll
    for (int ii = 0; ii < 4; ii++) {
        const int idx = tid + ii * 256;
        const int r = idx >> 4;
        const int c = (idx & 15) * 4;
        float4 v = *(const float4*)&YS[r * 72 + c];
        const int n = n0 + c;
        if (z == 3) {
            v.x = 1.f / (1.f + expf(-(v.x + Wob[n + 0])));
            v.y = 1.f / (1.f + expf(-(v.y + Wob[n + 1])));
            v.z = 1.f / (1.f + expf(-(v.z + Wob[n + 2])));
            v.w = 1.f / (1.f + expf(-(v.w + Wob[n + 3])));
        } else if (z != 2) {
            v.x *= QK_SCALE; v.y *= QK_SCALE; v.z *= QK_SCALE; v.w *= QK_SCALE;
        }
        *(float4*)&Y[(size_t)(m0 + r) * DH + n] = v;
    }
}

// ============================================================
// out_proj: split-K=8 wmma -> partials, grid (16 n, 2 m, 8 kz)
// ============================================================
__global__ void __launch_bounds__(256)
outproj_kernel(const float* __restrict__ P)
{
    __shared__ __align__(16) char raw[2 * BUF_B];

    const int z  = blockIdx.z;
    const int m0 = blockIdx.y * 64;
    const int n0 = blockIdx.x * 64;

    gemm_wmma(raw, g_hh, P, m0, n0, z * 128, 128 / KCH);
    __syncthreads();

    const float* YS = (const float*)raw;
    float* __restrict__ Yp = g_part[z];
    const int tid = threadIdx.x;
    #pragma unroll
    for (int ii = 0; ii < 4; ii++) {
        const int idx = tid + ii * 256;
        const int r = idx >> 4;
        const int c = (idx & 15) * 4;
        const float4 v = *(const float4*)&YS[r * 72 + c];
        *(float4*)&Yp[(size_t)(m0 + r) * DM + n0 + c] = v;
    }
}

__global__ void __launch_bounds__(256)
outproj_reduce_kernel(float* __restrict__ out_h)
{
    const int idx = blockIdx.x * 256 + threadIdx.x; // float4 index
    float4 r = {0.f, 0.f, 0.f, 0.f};
    #pragma unroll
    for (int p = 0; p < 8; p++) {
        const float4 a = ((const float4*)g_part[p])[idx];
        r.x += a.x; r.y += a.y; r.z += a.z; r.w += a.w;
    }
    ((float4*)out_h)[idx] = r;
}

// ============================================================
// Merged gating + n_t + denom (one block per batch, 256 thr)
// ============================================================
__global__ void __launch_bounds__(256)
gate_ndenom_kernel(const float* __restrict__ x,
                   const float* __restrict__ wi, const float* __restrict__ wib,
                   const float* __restrict__ wf, const float* __restrict__ wfb,
                   const float* __restrict__ mprev,
                   const float* __restrict__ nprev,
                   float* __restrict__ out_m, float* __restrict__ out_n)
{
    const int b = blockIdx.x;
    const int t = threadIdx.x;

    const float4 xv = ((const float4*)(x + (size_t)b * DM))[t];
    const float4 iv = ((const float4*)wi)[t];
    const float4 fv = ((const float4*)wf)[t];
    float si = xv.x * iv.x + xv.y * iv.y + xv.z * iv.z + xv.w * iv.w;
    float sf = xv.x * fv.x + xv.y * fv.y + xv.z * fv.z + xv.w * fv.w;

    __shared__ float sbi[8], sbf[8], sgate[2];
    si = warp_sum(si); sf = warp_sum(sf);
    if ((t & 31) == 0) { sbi[t >> 5] = si; sbf[t >> 5] = sf; }
    __syncthreads();
    if (t == 0) {
        float zi = 0.f, zf = 0.f;
        #pragma unroll
        for (int w = 0; w < 8; w++) { zi += sbi[w]; zf += sbf[w]; }
        zi += *wib; zf += *wfb;
        const float mp = mprev[b];
        const float mt = fmaxf(zf + mp, zi);
        const float ip = expf(zi - mt);
        const float fp = expf(zf + mp - mt);
        out_m[b] = mt;
        g_ip[b] = ip; g_fp[b] = fp;
        sgate[0] = ip; sgate[1] = fp;
    }
    __syncthreads();

    const float ip = sgate[0];
    const float f  = sgate[1];
    const float4 np = ((const float4*)(nprev + (size_t)b * DH))[t];
    const float4 kv = ((const float4*)(g_k   + (size_t)b * DH))[t];
    const float4 qv = ((const float4*)(g_q   + (size_t)b * DH))[t];
    float4 n;
    n.x = f * np.x + ip * kv.x;
    n.y = f * np.y + ip * kv.y;
    n.z = f * np.z + ip * kv.z;
    n.w = f * np.w + ip * kv.w;
    ((float4*)(out_n + (size_t)b * DH))[t] = n;

    float s = n.x * qv.x + n.y * qv.y + n.z * qv.z + n.w * qv.w;
    s = warp_sum(s);
    if ((t & 31) == 0) sbi[t >> 5] = s;
    __syncthreads();
    if (t == 0) {
        float tot = 0.f;
        #pragma unroll
        for (int w = 0; w < 8; w++) tot += sbi[w];
        g_den[b] = fmaxf(fabsf(tot), 1.f);
    }
}

// ============================================================
// Fused C update + Cq matvec + h_head  (HBM-bound) — unchanged
// grid (64 row-chunks, 128 batches), 512 threads = 16 warps.
// ============================================================
__global__ void __launch_bounds__(512)
c_update_kernel(const float* __restrict__ Cprev, float* __restrict__ Cout)
{
    const int b = blockIdx.y;
    __shared__ float4 ks4[256];
    __shared__ float4 qs4[256];
    if (threadIdx.x < 256) {
        const int t = threadIdx.x;
        ks4[t] = ((const float4*)(g_k + (size_t)b * DH))[t];
        qs4[t] = ((const float4*)(g_q + (size_t)b * DH))[t];
    }
    __syncthreads();

    const int warp = threadIdx.x >> 5;
    const int lane = threadIdx.x & 31;
    const int i = blockIdx.x * 16 + warp;

    const float f  = g_fp[b];
    const float iv = g_ip[b] * g_v[(size_t)b * DH + i];

    const float4* __restrict__ cp = (const float4*)(Cprev + ((size_t)b * DH + i) * DH);
    float4* __restrict__ co = (float4*)(Cout + ((size_t)b * DH + i) * DH);

    float4 c[8];
    #pragma unroll
    for (int u = 0; u < 8; u++) c[u] = __ldcs(&cp[u * 32 + lane]);

    float acc = 0.f;
    #pragma unroll
    for (int u = 0; u < 8; u++) {
        const int j4 = u * 32 + lane;
        const float4 k4 = ks4[j4];
        const float4 q4 = qs4[j4];
        float4 o;
        o.x = fmaf(f, c[u].x, iv * k4.x);
        o.y = fmaf(f, c[u].y, iv * k4.y);
        o.z = fmaf(f, c[u].z, iv * k4.z);
        o.w = fmaf(f, c[u].w, iv * k4.w);
        acc = fmaf(o.x, q4.x, acc);
        acc = fmaf(o.y, q4.y, acc);
        acc = fmaf(o.z, q4.z, acc);
        acc = fmaf(o.w, q4.w, acc);
        __stcs(&co[j4], o);
    }
    acc = warp_sum(acc);
    if (lane == 0)
        g_hh[(size_t)b * DH + i] = g_o[(size_t)b * DH + i] * acc / g_den[b];
}

// ============================================================
// launch (serial single-stream)
// ============================================================
extern "C" void kernel_launch(void* const* d_in, const int* in_sizes, int n_in,
                              void* d_out, int out_size)
{
    const float* x     = (const float*)d_in[0];
    const float* Cprev = (const float*)d_in[1];
    const float* nprev = (const float*)d_in[2];
    const float* mprev = (const float*)d_in[3];
    const float* Wq    = (const float*)d_in[4];
    const float* Wk    = (const float*)d_in[5];
    const float* Wv    = (const float*)d_in[6];
    const float* wi    = (const float*)d_in[7];
    const float* wib   = (const float*)d_in[8];
    const float* wf    = (const float*)d_in[9];
    const float* wfb   = (const float*)d_in[10];
    const float* Wo    = (const float*)d_in[11];
    const float* Wob   = (const float*)d_in[12];
    const float* P     = (const float*)d_in[13];

    float* out   = (float*)d_out;
    float* out_h = out;                                        // (B, 1024)
    float* out_c = out + (size_t)BATCH * DM;                   // (B, 1024, 1024)
    float* out_n = out_c + (size_t)BATCH * DH * DH;            // (B, 1024)
    float* out_m = out_n + (size_t)BATCH * DH;                 // (B,)

    proj_kernel<<<dim3(16, 2, 4), 256>>>(x, Wq, Wk, Wv, Wo, Wob);
    gate_ndenom_kernel<<<BATCH, 256>>>(x, wi, wib, wf, wfb, mprev, nprev, out_m, out_n);
    c_update_kernel<<<dim3(64, BATCH), 512>>>(Cprev, out_c);
    outproj_kernel<<<dim3(16, 2, 8), 256>>>(P);
    outproj_reduce_kernel<<<128, 256>>>(out_h);
}

// round 12
// speedup vs baseline: 1.3042x; 1.0292x over previous
#include <cuda_runtime.h>
#include <cuda_bf16.h>
#include <mma.h>
#include <math.h>

using namespace nvcuda;

#define DH 1024
#define DM 1024
#define BATCH 128
static constexpr float QK_SCALE = 0.03125f; // 1/sqrt(1024)

// -------- scratch (no allocations allowed) --------
__device__ __nv_bfloat16 g_xh[BATCH * DM];   // x split hi
__device__ __nv_bfloat16 g_xl[BATCH * DM];   // x split lo
__device__ __nv_bfloat16 g_hhh[BATCH * DH];  // h_head split hi
__device__ __nv_bfloat16 g_hhl[BATCH * DH];  // h_head split lo
__device__ float g_q[BATCH * DH];
__device__ float g_k[BATCH * DH];
__device__ float g_v[BATCH * DH];
__device__ float g_o[BATCH * DH];
__device__ float g_part[8][BATCH * DM];      // split-K partials for out_proj
__device__ float g_ip[BATCH];
__device__ float g_fp[BATCH];
__device__ float g_den[BATCH];

__device__ __forceinline__ float warp_sum(float v) {
    #pragma unroll
    for (int s = 16; s; s >>= 1) v += __shfl_xor_sync(0xffffffffu, v, s);
    return v;
}

// ============================================================
// Split-bf16 WMMA GEMM core. X comes PRE-SPLIT (bf16 hi/lo in
// gmem); W is fp32 and split in-kernel. One-sync double-buffered.
//   Y[m,n] = sum_k X[m,k] * W[n,k]    (64x64 tile per block)
// smem: 2 buffers x {XH,XL,WH,WL}[64][40] bf16; fp32 epilogue
// tile YS[64][72] overlays buffer 0 after the final sync.
// 256 threads = 8 warps: wm = warp>>1 (16 rows), wn = warp&1.
// ============================================================
#define KCH 32
#define BLD 40
#define ARR_B (64 * BLD * 2)         // 5120 B per array
#define BUF_B (4 * ARR_B)            // 20480 B per buffer set

__device__ __forceinline__ __nv_bfloat16* sm_arr(char* raw, int buf, int arr) {
    return (__nv_bfloat16*)(raw + buf * BUF_B + arr * ARR_B);
}

__device__ __forceinline__ void split_store_row(
    __nv_bfloat16* H, __nv_bfloat16* L, int r, int c, float4 v)
{
    __nv_bfloat16 hx = __float2bfloat16(v.x);
    __nv_bfloat16 hy = __float2bfloat16(v.y);
    __nv_bfloat16 hz = __float2bfloat16(v.z);
    __nv_bfloat16 hw = __float2bfloat16(v.w);
    __nv_bfloat16 lx = __float2bfloat16(v.x - __bfloat162float(hx));
    __nv_bfloat16 ly = __float2bfloat16(v.y - __bfloat162float(hy));
    __nv_bfloat16 lz = __float2bfloat16(v.z - __bfloat162float(hz));
    __nv_bfloat16 lw = __float2bfloat16(v.w - __bfloat162float(hw));
    *(__nv_bfloat162*)&H[r * BLD + c]     = __nv_bfloat162(hx, hy);
    *(__nv_bfloat162*)&H[r * BLD + c + 2] = __nv_bfloat162(hz, hw);
    *(__nv_bfloat162*)&L[r * BLD + c]     = __nv_bfloat162(lx, ly);
    *(__nv_bfloat162*)&L[r * BLD + c + 2] = __nv_bfloat162(lz, lw);
}

// Caller must __syncthreads() after return before reading YS.
__device__ __forceinline__ void gemm_wmma_ps(
    char* raw,
    const __nv_bfloat16* __restrict__ XHg, const __nv_bfloat16* __restrict__ XLg,
    const float* __restrict__ W,
    int m0, int n0, int kbeg, int nchunks)
{
    const int tid  = threadIdx.x;
    const int warp = tid >> 5;
    const int wm   = warp >> 1;
    const int wn   = warp & 1;

    wmma::fragment<wmma::accumulator, 16, 16, 16, float> acc[2];
    wmma::fill_fragment(acc[0], 0.f);
    wmma::fill_fragment(acc[1], 0.f);

    // X loader: pre-split bf16 copy. 64 rows x 32 cols per chunk.
    const int xr = tid >> 2;               // 0..63
    const int xc = (tid & 3) * 8;          // 0,8,16,24
    const __nv_bfloat16* __restrict__ xhg = XHg + (size_t)(m0 + xr) * DM + kbeg + xc;
    const __nv_bfloat16* __restrict__ xlg = XLg + (size_t)(m0 + xr) * DM + kbeg + xc;

    // W loader: fp32, split in-kernel. rows wr, wr+32.
    const int wr = tid >> 3;               // 0..31
    const int wc = (tid & 7) * 4;          // 0..28
    const float* __restrict__ wg  = W + (size_t)(n0 + wr) * DM + kbeg + wc;
    const float* __restrict__ wg2 = wg + 32 * DM;

    uint4  pxh = *(const uint4*)xhg;
    uint4  pxl = *(const uint4*)xlg;
    float4 pw0 = *(const float4*)wg;
    float4 pw1 = *(const float4*)wg2;

    // stage chunk 0 into buffer 0
    *(uint4*)&sm_arr(raw,0,0)[xr * BLD + xc] = pxh;
    *(uint4*)&sm_arr(raw,0,1)[xr * BLD + xc] = pxl;
    split_store_row(sm_arr(raw,0,2), sm_arr(raw,0,3), wr,      wc, pw0);
    split_store_row(sm_arr(raw,0,2), sm_arr(raw,0,3), wr + 32, wc, pw1);
    __syncthreads();

    for (int kc = 0; kc < nchunks; kc++) {
        const int b = kc & 1;
        if (kc + 1 < nchunks) {
            pxh = *(const uint4*)(xhg + (kc + 1) * KCH);
            pxl = *(const uint4*)(xlg + (kc + 1) * KCH);
            pw0 = *(const float4*)(wg  + (kc + 1) * KCH);
            pw1 = *(const float4*)(wg2 + (kc + 1) * KCH);
        }

        const __nv_bfloat16* XH = sm_arr(raw, b, 0);
        const __nv_bfloat16* XL = sm_arr(raw, b, 1);
        const __nv_bfloat16* WH = sm_arr(raw, b, 2);
        const __nv_bfloat16* WL = sm_arr(raw, b, 3);

        #pragma unroll
        for (int ks = 0; ks < KCH; ks += 16) {
            wmma::fragment<wmma::matrix_a, 16, 16, 16, __nv_bfloat16, wmma::row_major> ah, al;
            wmma::load_matrix_sync(ah, &XH[(wm * 16) * BLD + ks], BLD);
            wmma::load_matrix_sync(al, &XL[(wm * 16) * BLD + ks], BLD);
            #pragma unroll
            for (int t = 0; t < 2; t++) {
                wmma::fragment<wmma::matrix_b, 16, 16, 16, __nv_bfloat16, wmma::col_major> bh, bl;
                wmma::load_matrix_sync(bh, &WH[(wn * 32 + t * 16) * BLD + ks], BLD);
                wmma::load_matrix_sync(bl, &WL[(wn * 32 + t * 16) * BLD + ks], BLD);
                wmma::mma_sync(acc[t], ah, bh, acc[t]);
                wmma::mma_sync(acc[t], ah, bl, acc[t]);
                wmma::mma_sync(acc[t], al, bh, acc[t]);
            }
        }

        if (kc + 1 < nchunks) {
            const int nb = b ^ 1;
            *(uint4*)&sm_arr(raw,nb,0)[xr * BLD + xc] = pxh;
            *(uint4*)&sm_arr(raw,nb,1)[xr * BLD + xc] = pxl;
            split_store_row(sm_arr(raw,nb,2), sm_arr(raw,nb,3), wr,      wc, pw0);
            split_store_row(sm_arr(raw,nb,2), sm_arr(raw,nb,3), wr + 32, wc, pw1);
            __syncthreads();
        }
    }

    __syncthreads();
    float* YS = (float*)raw;
    wmma::store_matrix_sync(&YS[(wm * 16) * 72 + wn * 32],      acc[0], 72, wmma::mem_row_major);
    wmma::store_matrix_sync(&YS[(wm * 16) * 72 + wn * 32 + 16], acc[1], 72, wmma::mem_row_major);
}

// ============================================================
// gate + x pre-split (one block per batch, 256 thr):
//   writes g_xh/g_xl (bf16 split of x), z_i/z_f dots, m_t, ip/fp
// ============================================================
__global__ void __launch_bounds__(256)
gate_presplit_kernel(const float* __restrict__ x,
                     const float* __restrict__ wi, const float* __restrict__ wib,
                     const float* __restrict__ wf, const float* __restrict__ wfb,
                     const float* __restrict__ mprev,
                     float* __restrict__ out_m)
{
    const int b = blockIdx.x;
    const int t = threadIdx.x;
    const float4 xv = ((const float4*)(x + (size_t)b * DM))[t];
    const float4 iv = ((const float4*)wi)[t];
    const float4 fv = ((const float4*)wf)[t];

    // split x -> bf16 hi/lo
    __nv_bfloat16 hx = __float2bfloat16(xv.x);
    __nv_bfloat16 hy = __float2bfloat16(xv.y);
    __nv_bfloat16 hz = __float2bfloat16(xv.z);
    __nv_bfloat16 hw = __float2bfloat16(xv.w);
    const size_t o = (size_t)b * DM + t * 4;
    *(__nv_bfloat162*)&g_xh[o]     = __nv_bfloat162(hx, hy);
    *(__nv_bfloat162*)&g_xh[o + 2] = __nv_bfloat162(hz, hw);
    *(__nv_bfloat162*)&g_xl[o]     = __nv_bfloat162(
        __float2bfloat16(xv.x - __bfloat162float(hx)),
        __float2bfloat16(xv.y - __bfloat162float(hy)));
    *(__nv_bfloat162*)&g_xl[o + 2] = __nv_bfloat162(
        __float2bfloat16(xv.z - __bfloat162float(hz)),
        __float2bfloat16(xv.w - __bfloat162float(hw)));

    float si = xv.x * iv.x + xv.y * iv.y + xv.z * iv.z + xv.w * iv.w;
    float sf = xv.x * fv.x + xv.y * fv.y + xv.z * fv.z + xv.w * fv.w;

    __shared__ float sbi[8], sbf[8];
    si = warp_sum(si); sf = warp_sum(sf);
    if ((t & 31) == 0) { sbi[t >> 5] = si; sbf[t >> 5] = sf; }
    __syncthreads();
    if (t == 0) {
        float zi = 0.f, zf = 0.f;
        #pragma unroll
        for (int w = 0; w < 8; w++) { zi += sbi[w]; zf += sbf[w]; }
        zi += *wib; zf += *wfb;
        const float mp = mprev[b];
        const float mt = fmaxf(zf + mp, zi);
        out_m[b] = mt;
        g_ip[b] = expf(zi - mt);
        g_fp[b] = expf(zf + mp - mt);
    }
}

// ============================================================
// Projections q/k/v/sigmoid(o): grid (16 n, 2 m, 4 mat), 256 thr
// ============================================================
__global__ void __launch_bounds__(256)
proj_kernel(const float* __restrict__ Wq, const float* __restrict__ Wk,
            const float* __restrict__ Wv, const float* __restrict__ Wo,
            const float* __restrict__ Wob)
{
    __shared__ __align__(16) char raw[2 * BUF_B];

    const int z = blockIdx.z;
    const float* __restrict__ W = (z == 0) ? Wq : (z == 1) ? Wk : (z == 2) ? Wv : Wo;
    float* __restrict__ Y = (z == 0) ? g_q : (z == 1) ? g_k : (z == 2) ? g_v : g_o;

    const int m0 = blockIdx.y * 64;
    const int n0 = blockIdx.x * 64;

    gemm_wmma_ps(raw, g_xh, g_xl, W, m0, n0, 0, DM / KCH);
    __syncthreads();

    const float* YS = (const float*)raw;
    const int tid = threadIdx.x;
    #pragma unroll
    for (int ii = 0; ii < 4; ii++) {
        const int idx = tid + ii * 256;
        const int r = idx >> 4;
        const int c = (idx & 15) * 4;
        float4 v = *(const float4*)&YS[r * 72 + c];
        const int n = n0 + c;
        if (z == 3) {
            v.x = 1.f / (1.f + expf(-(v.x + Wob[n + 0])));
            v.y = 1.f / (1.f + expf(-(v.y + Wob[n + 1])));
            v.z = 1.f / (1.f + expf(-(v.z + Wob[n + 2])));
            v.w = 1.f / (1.f + expf(-(v.w + Wob[n + 3])));
        } else if (z != 2) {
            v.x *= QK_SCALE; v.y *= QK_SCALE; v.z *= QK_SCALE; v.w *= QK_SCALE;
        }
        *(float4*)&Y[(size_t)(m0 + r) * DH + n] = v;
    }
}

// ============================================================
// n_t + denom (one block per batch, 256 thr)
// ============================================================
__global__ void __launch_bounds__(256)
ndenom_kernel(const float* __restrict__ nprev, float* __restrict__ out_n)
{
    const int b = blockIdx.x;
    const int t = threadIdx.x;
    const float ip = g_ip[b];
    const float f  = g_fp[b];
    const float4 np = ((const float4*)(nprev + (size_t)b * DH))[t];
    const float4 kv = ((const float4*)(g_k   + (size_t)b * DH))[t];
    const float4 qv = ((const float4*)(g_q   + (size_t)b * DH))[t];
    float4 n;
    n.x = f * np.x + ip * kv.x;
    n.y = f * np.y + ip * kv.y;
    n.z = f * np.z + ip * kv.z;
    n.w = f * np.w + ip * kv.w;
    ((float4*)(out_n + (size_t)b * DH))[t] = n;

    float s = n.x * qv.x + n.y * qv.y + n.z * qv.z + n.w * qv.w;
    __shared__ float sb[8];
    s = warp_sum(s);
    if ((t & 31) == 0) sb[t >> 5] = s;
    __syncthreads();
    if (t == 0) {
        float tot = 0.f;
        #pragma unroll
        for (int w = 0; w < 8; w++) tot += sb[w];
        g_den[b] = fmaxf(fabsf(tot), 1.f);
    }
}

// ============================================================
// Fused C update + Cq matvec + h_head (HBM-bound). Epilogue now
// writes h_head pre-split to bf16 hi/lo for outproj.
// grid (64 row-chunks, 128 batches), 512 threads = 16 warps.
// ============================================================
__global__ void __launch_bounds__(512)
c_update_kernel(const float* __restrict__ Cprev, float* __restrict__ Cout)
{
    const int b = blockIdx.y;
    __shared__ float4 ks4[256];
    __shared__ float4 qs4[256];
    if (threadIdx.x < 256) {
        const int t = threadIdx.x;
        ks4[t] = ((const float4*)(g_k + (size_t)b * DH))[t];
        qs4[t] = ((const float4*)(g_q + (size_t)b * DH))[t];
    }
    __syncthreads();

    const int warp = threadIdx.x >> 5;
    const int lane = threadIdx.x & 31;
    const int i = blockIdx.x * 16 + warp;

    const float f  = g_fp[b];
    const float iv = g_ip[b] * g_v[(size_t)b * DH + i];

    const float4* __restrict__ cp = (const float4*)(Cprev + ((size_t)b * DH + i) * DH);
    float4* __restrict__ co = (float4*)(Cout + ((size_t)b * DH + i) * DH);

    float4 c[8];
    #pragma unroll
    for (int u = 0; u < 8; u++) c[u] = __ldcs(&cp[u * 32 + lane]);

    float acc = 0.f;
    #pragma unroll
    for (int u = 0; u < 8; u++) {
        const int j4 = u * 32 + lane;
        const float4 k4 = ks4[j4];
        const float4 q4 = qs4[j4];
        float4 o;
        o.x = fmaf(f, c[u].x, iv * k4.x);
        o.y = fmaf(f, c[u].y, iv * k4.y);
        o.z = fmaf(f, c[u].z, iv * k4.z);
        o.w = fmaf(f, c[u].w, iv * k4.w);
        acc = fmaf(o.x, q4.x, acc);
        acc = fmaf(o.y, q4.y, acc);
        acc = fmaf(o.z, q4.z, acc);
        acc = fmaf(o.w, q4.w, acc);
        __stcs(&co[j4], o);
    }
    acc = warp_sum(acc);
    if (lane == 0) {
        const float hh = g_o[(size_t)b * DH + i] * acc / g_den[b];
        const __nv_bfloat16 hi = __float2bfloat16(hh);
        g_hhh[(size_t)b * DH + i] = hi;
        g_hhl[(size_t)b * DH + i] = __float2bfloat16(hh - __bfloat162float(hi));
    }
}

// ============================================================
// out_proj: split-K=8 wmma -> partials, grid (16 n, 2 m, 8 kz)
// ============================================================
__global__ void __launch_bounds__(256)
outproj_kernel(const float* __restrict__ P)
{
    __shared__ __align__(16) char raw[2 * BUF_B];

    const int z  = blockIdx.z;
    const int m0 = blockIdx.y * 64;
    const int n0 = blockIdx.x * 64;

    gemm_wmma_ps(raw, g_hhh, g_hhl, P, m0, n0, z * 128, 128 / KCH);
    __syncthreads();

    const float* YS = (const float*)raw;
    float* __restrict__ Yp = g_part[z];
    const int tid = threadIdx.x;
    #pragma unroll
    for (int ii = 0; ii < 4; ii++) {
        const int idx = tid + ii * 256;
        const int r = idx >> 4;
        const int c = (idx & 15) * 4;
        const float4 v = *(const float4*)&YS[r * 72 + c];
        *(float4*)&Yp[(size_t)(m0 + r) * DM + n0 + c] = v;
    }
}

__global__ void __launch_bounds__(256)
outproj_reduce_kernel(float* __restrict__ out_h)
{
    const int idx = blockIdx.x * 256 + threadIdx.x; // float4 index
    float4 r = {0.f, 0.f, 0.f, 0.f};
    #pragma unroll
    for (int p = 0; p < 8; p++) {
        const float4 a = ((const float4*)g_part[p])[idx];
        r.x += a.x; r.y += a.y; r.z += a.z; r.w += a.w;
    }
    ((float4*)out_h)[idx] = r;
}

// ============================================================
// launch (serial single-stream)
// ============================================================
extern "C" void kernel_launch(void* const* d_in, const int* in_sizes, int n_in,
                              void* d_out, int out_size)
{
    const float* x     = (const float*)d_in[0];
    const float* Cprev = (const float*)d_in[1];
    const float* nprev = (const float*)d_in[2];
    const float* mprev = (const float*)d_in[3];
    const float* Wq    = (const float*)d_in[4];
    const float* Wk    = (const float*)d_in[5];
    const float* Wv    = (const float*)d_in[6];
    const float* wi    = (const float*)d_in[7];
    const float* wib   = (const float*)d_in[8];
    const float* wf    = (const float*)d_in[9];
    const float* wfb   = (const float*)d_in[10];
    const float* Wo    = (const float*)d_in[11];
    const float* Wob   = (const float*)d_in[12];
    const float* P     = (const float*)d_in[13];

    float* out   = (float*)d_out;
    float* out_h = out;                                        // (B, 1024)
    float* out_c = out + (size_t)BATCH * DM;                   // (B, 1024, 1024)
    float* out_n = out_c + (size_t)BATCH * DH * DH;            // (B, 1024)
    float* out_m = out_n + (size_t)BATCH * DH;                 // (B,)

    gate_presplit_kernel<<<BATCH, 256>>>(x, wi, wib, wf, wfb, mprev, out_m);
    proj_kernel<<<dim3(16, 2, 4), 256>>>(Wq, Wk, Wv, Wo, Wob);
    ndenom_kernel<<<BATCH, 256>>>(nprev, out_n);
    c_update_kernel<<<dim3(64, BATCH), 512>>>(Cprev, out_c);
    outproj_kernel<<<dim3(16, 2, 8), 256>>>(P);
    outproj_reduce_kernel<<<128, 256>>>(out_h);
}